// round 14
// baseline (speedup 1.0000x reference)
#include <cuda_runtime.h>
#include <cuda_fp16.h>
#include <cstdint>

#define LOCN   40001
#define BATCH  1024
#define TSTEPS 256

#define ROWS_PER_CTA 7
#define NCTA ((BATCH + ROWS_PER_CTA - 1) / ROWS_PER_CTA)   // 147
#define HS2 120                              // fp16 h row stride
#define SRW 608                              // staging row stride in halfs

// dynamic smem layout for kernD (bytes)
#define OFF_HBUF 0                            // 2*16*120*2 = 7680
#define OFF_STG  7680                         // 3*7*608*2  = 25536
#define OFF_TRAJ 33216                        // 7*256*2    = 3584
#define OFF_IDXP 36800                        // 7*256*4    = 7168
#define OFF_CT   43968                        // 7*256*4    = 7168
#define OFF_CS   51136                        // 7*256*4    = 7168
#define OFF_PT   58304                        // 9200*2     = 18400
#define OFF_PS   76704                        // 9200*2     = 18400
#define DSM_TOTAL 95104

// ---------------- device scratch ----------------
// NOTE: Gloc/W16 first-400 columns are GATE-INTERLEAVED: stored col s = 4*j + gate
__device__ __half g_Gloc[(size_t)LOCN * 600];
__device__ float  g_Pt[92 * 100];
__device__ float  g_Ps[92 * 100];
__device__ __half g_emb16[(size_t)LOCN * 112];
__device__ __half g_W16[112 * 608];

// ---------------- helpers ----------------
__device__ __forceinline__ float sigf(float x) { return 1.f / (1.f + __expf(-x)); }
__device__ __forceinline__ float tanh_fast(float x) { return 1.f - 2.f / (1.f + __expf(2.f * x)); }

__device__ __forceinline__ uint32_t smem_u32(const void* p) {
    uint32_t a;
    asm("{ .reg .u64 t; cvta.to.shared.u64 t, %1; cvt.u32.u64 %0, t; }" : "=r"(a) : "l"(p));
    return a;
}

// =======================================================================
// Kernel P: fp16 conversion. W16 cols <400 gate-interleaved (s = 4j+gate).
// =======================================================================
__global__ void kernP(const float* __restrict__ emb_loc,
                      const float* __restrict__ W_ih,
                      const float* __restrict__ W_xt,
                      const float* __restrict__ W_xs)
{
    const int NE = LOCN * 28;
    int i = blockIdx.x * blockDim.x + threadIdx.x;
    if (i < NE) {
        int row = i / 28, k4 = i % 28;
        int k = k4 * 4;
        float4 v = make_float4(0.f, 0.f, 0.f, 0.f);
        if (k < 100) v = *(const float4*)(emb_loc + (size_t)row * 100 + k);
        __half2 h0 = __floats2half2_rn(v.x, v.y);
        __half2 h1 = __floats2half2_rn(v.z, v.w);
        uint2 st;
        st.x = *reinterpret_cast<unsigned*>(&h0);
        st.y = *reinterpret_cast<unsigned*>(&h1);
        *(uint2*)(g_emb16 + (size_t)row * 112 + k) = st;
    } else {
        int j = i - NE;
        if (j < 112 * 152) {
            int k = j / 152, c4 = j % 152;
            int c = c4 * 4;
            float v[4] = {0.f, 0.f, 0.f, 0.f};
            if (k < 100) {
#pragma unroll
                for (int d = 0; d < 4; d++) {
                    int col = c + d;
                    if (col < 400) {
                        int a = (col & 3) * 100 + (col >> 2);    // gate-interleave
                        v[d] = W_ih[k * 400 + a];
                    }
                    else if (col < 500) v[d] = W_xt[k * 100 + (col - 400)];
                    else if (col < 600) v[d] = W_xs[k * 100 + (col - 500)];
                }
            }
            __half2 h0 = __floats2half2_rn(v[0], v[1]);
            __half2 h1 = __floats2half2_rn(v[2], v[3]);
            uint2 st;
            st.x = *reinterpret_cast<unsigned*>(&h0);
            st.y = *reinterpret_cast<unsigned*>(&h1);
            *(uint2*)(g_W16 + k * 608 + c) = st;
        }
    }
}

// =======================================================================
// Kernel A (tensor-core, fp16 inputs). Bias lookup follows interleaving.
// =======================================================================
#define KA_AS 120

__global__ void __launch_bounds__(128)
kernA(const float* __restrict__ b,
      const float* __restrict__ b_t,
      const float* __restrict__ b_s)
{
    __shared__ __align__(16) __half As[64 * KA_AS];
    __shared__ __align__(16) __half Bs[112 * KA_AS];

    const int tid = threadIdx.x;
    const int warp = tid >> 5, lane = tid & 31;
    const int n0 = blockIdx.x * 120;
    const int m0 = blockIdx.y * 64;

    for (int i = tid; i < 64 * 14; i += 128) {
        int r = i / 14, c = i % 14;
        int row = m0 + r; if (row >= LOCN) row = LOCN - 1;
        uint4 v = *(const uint4*)(g_emb16 + (size_t)row * 112 + c * 8);
        *(uint4*)(As + r * KA_AS + c * 8) = v;
    }
    for (int i = tid; i < 112 * 15; i += 128) {
        int k = i / 15, c = i % 15;
        uint4 v = *(const uint4*)(g_W16 + k * 608 + n0 + c * 8);
        *(uint4*)(Bs + k * KA_AS + c * 8) = v;
    }
    __syncthreads();

    const int g8 = lane >> 3, lr = lane & 7;

    float acc[15][4];
#pragma unroll
    for (int i = 0; i < 15; i++) { acc[i][0] = acc[i][1] = acc[i][2] = acc[i][3] = 0.f; }

    const int a_row = warp * 16 + (g8 & 1) * 8 + lr;
    const int a_kof = (g8 >> 1) * 8;
    const uint32_t a_base = smem_u32(&As[a_row * KA_AS + a_kof]);
    const int b_kof = (g8 & 1) * 8 + lr;
    const int b_nof = (g8 >> 1) * 8;
    const uint32_t b_base = smem_u32(&Bs[b_kof * KA_AS + b_nof]);
    const int b2_kof = ((lane >> 3) & 1) * 8 + lr;
    const uint32_t b2_base = smem_u32(&Bs[b2_kof * KA_AS + 112]);

#pragma unroll
    for (int kc = 0; kc < 7; kc++) {
        uint32_t a0, a1, a2, a3;
        asm volatile("ldmatrix.sync.aligned.m8n8.x4.shared.b16 {%0,%1,%2,%3}, [%4];"
                     : "=r"(a0), "=r"(a1), "=r"(a2), "=r"(a3)
                     : "r"(a_base + kc * 16 * 2));
#pragma unroll
        for (int pr = 0; pr < 7; pr++) {
            uint32_t b0, b1, b2, b3;
            asm volatile("ldmatrix.sync.aligned.m8n8.x4.trans.shared.b16 {%0,%1,%2,%3}, [%4];"
                         : "=r"(b0), "=r"(b1), "=r"(b2), "=r"(b3)
                         : "r"(b_base + (kc * 16 * KA_AS + pr * 16) * 2));
            asm volatile("mma.sync.aligned.m16n8k16.row.col.f32.f16.f16.f32 "
                         "{%0,%1,%2,%3}, {%4,%5,%6,%7}, {%8,%9}, {%0,%1,%2,%3};"
                         : "+f"(acc[2 * pr][0]), "+f"(acc[2 * pr][1]),
                           "+f"(acc[2 * pr][2]), "+f"(acc[2 * pr][3])
                         : "r"(a0), "r"(a1), "r"(a2), "r"(a3), "r"(b0), "r"(b1));
            asm volatile("mma.sync.aligned.m16n8k16.row.col.f32.f16.f16.f32 "
                         "{%0,%1,%2,%3}, {%4,%5,%6,%7}, {%8,%9}, {%0,%1,%2,%3};"
                         : "+f"(acc[2 * pr + 1][0]), "+f"(acc[2 * pr + 1][1]),
                           "+f"(acc[2 * pr + 1][2]), "+f"(acc[2 * pr + 1][3])
                         : "r"(a0), "r"(a1), "r"(a2), "r"(a3), "r"(b2), "r"(b3));
        }
        {
            uint32_t b0, b1;
            asm volatile("ldmatrix.sync.aligned.m8n8.x2.trans.shared.b16 {%0,%1}, [%2];"
                         : "=r"(b0), "=r"(b1)
                         : "r"(b2_base + kc * 16 * KA_AS * 2));
            asm volatile("mma.sync.aligned.m16n8k16.row.col.f32.f16.f16.f32 "
                         "{%0,%1,%2,%3}, {%4,%5,%6,%7}, {%8,%9}, {%0,%1,%2,%3};"
                         : "+f"(acc[14][0]), "+f"(acc[14][1]),
                           "+f"(acc[14][2]), "+f"(acc[14][3])
                         : "r"(a0), "r"(a1), "r"(a2), "r"(a3), "r"(b0), "r"(b1));
        }
    }

    const int row_lo = m0 + warp * 16 + (lane >> 2);
    const int row_hi = row_lo + 8;
#pragma unroll
    for (int nt = 0; nt < 15; nt++) {
        int col = n0 + nt * 8 + (lane & 3) * 2;
        float bias0, bias1;
        if (col < 400) {          // interleaved: s=4j+gate (s, s+1 same j)
            bias0 = b[(col & 3) * 100 + (col >> 2)];
            bias1 = b[((col + 1) & 3) * 100 + ((col + 1) >> 2)];
        }
        else if (col < 500) { bias0 = b_t[col - 400]; bias1 = b_t[col - 399]; }
        else                { bias0 = b_s[col - 500]; bias1 = b_s[col - 499]; }
        __half2 lo = __floats2half2_rn(acc[nt][0] + bias0, acc[nt][1] + bias1);
        __half2 hi = __floats2half2_rn(acc[nt][2] + bias0, acc[nt][3] + bias1);
        if (row_lo < LOCN)
            *reinterpret_cast<unsigned*>(&g_Gloc[(size_t)row_lo * 600 + col]) =
                *reinterpret_cast<unsigned*>(&lo);
        if (row_hi < LOCN)
            *reinterpret_cast<unsigned*>(&g_Gloc[(size_t)row_hi * 600 + col]) =
                *reinterpret_cast<unsigned*>(&hi);
    }
}

// =======================================================================
// Kernel B (unchanged)
// =======================================================================
__global__ void kernB(const float* __restrict__ emb_t, const float* __restrict__ W_tt,
                      const float* __restrict__ emb_s, const float* __restrict__ W_ss)
{
    int i = blockIdx.x * blockDim.x + threadIdx.x;
    if (i >= 92 * 100 * 2) return;
    int which = i / 9200;
    int r = i % 9200;
    int s = r / 100, j = r % 100;
    const float* e = which ? emb_s : emb_t;
    const float* W = which ? W_ss : W_tt;
    float acc = 0.f;
#pragma unroll
    for (int d = 0; d < 12; d++) acc += e[s * 12 + d] * W[d * 100 + j];
    (which ? g_Ps : g_Pt)[s * 100 + j] = acc;
}

// =======================================================================
// Kernel D v12: gate-interleaved tensor-core recurrence, 1 barrier/step.
//  Lane pair (even,odd) of each 8-group holds all 4 gates of column j via
//  2 shfl_xor(1); each lane does one (row,j) LSTM update inline.
//  Interp coefs precomputed per (r,t). Triple-buffered cp.async gather.
// =======================================================================
__global__ void __launch_bounds__(800, 1)
kernD(const float* __restrict__ W_hh, float* __restrict__ out,
      const int* __restrict__ traj,
      const int* __restrict__ tu,   const int* __restrict__ tl,
      const int* __restrict__ tu_s, const int* __restrict__ tl_s,
      const int* __restrict__ su,   const int* __restrict__ sl,
      const int* __restrict__ su_s, const int* __restrict__ sl_s)
{
    extern __shared__ __align__(16) char dsm[];
    __half*   hbuf  = (__half*)(dsm + OFF_HBUF);   // [2][16][120]
    __half*   stg   = (__half*)(dsm + OFF_STG);    // [3][7][608]
    uint16_t* trajS = (uint16_t*)(dsm + OFF_TRAJ); // [7][256]
    uint32_t* idxP  = (uint32_t*)(dsm + OFF_IDXP); // [7][256] packed tl,tu,sl,su
    __half2*  cT    = (__half2*)(dsm + OFF_CT);    // [7][256] (ut*rdt, lt*rdt)
    __half2*  cS    = (__half2*)(dsm + OFF_CS);
    __half*   PtS   = (__half*)(dsm + OFF_PT);     // [92][100]
    __half*   PsS   = (__half*)(dsm + OFF_PS);

    const int tid = threadIdx.x;
    const int warp = tid >> 5, lane = tid & 31;
    const int row0 = blockIdx.x * ROWS_PER_CTA;

    // ---- B fragments: W_hh fp16, columns gate-interleaved ----
    uint32_t bf[7][2][2];
    {
        const int bn = 16 * warp + (lane >> 2);
        const int bk = 2 * (lane & 3);
#pragma unroll
        for (int c = 0; c < 7; c++) {
#pragma unroll
            for (int t = 0; t < 2; t++) {
                int n = bn + 8 * t;                          // stored col
                int an = (n & 3) * 100 + (n >> 2);           // actual W_hh col
#pragma unroll
                for (int rr = 0; rr < 2; rr++) {
                    int k = 16 * c + bk + 8 * rr;
                    float lo = (k     < 100) ? W_hh[k * 400 + an]       : 0.f;
                    float hi = (k + 1 < 100) ? W_hh[(k + 1) * 400 + an] : 0.f;
                    __half2 hv = __floats2half2_rn(lo, hi);
                    bf[c][t][rr] = *reinterpret_cast<uint32_t*>(&hv);
                }
            }
        }
    }

    // ---- lane constants ----
    const int qc = lane & 3;
    const bool qodd = (qc & 1);
    const int erow = lane >> 2;
    const bool evalid = (erow < ROWS_PER_CTA);
    const int er7 = evalid ? erow : 0;
    const int j_a = 4 * warp + (qc >> 1);
    const int uj = j_a + (qodd ? 2 : 0);                 // column this lane updates
    const int pA0 = er7 * SRW + 4 * j_a + (qodd ? 2 : 0);
    const float asl = qodd ? 2.f : 1.f;                  // slot0 act params (g=tanh)
    const float aal = qodd ? 2.f : 1.f;
    const float abl = qodd ? -1.f : 0.f;

    const uint32_t la0 = smem_u32(hbuf + (lane & 15) * HS2 + (lane >> 4) * 8);
    const uint32_t la1 = la0 + 16 * HS2 * 2;

    const bool sact = (tid < 525);
    const int r_s = tid / 75, c_s = tid % 75;
    const uint32_t stg_u32 = smem_u32(stg);

    // ---- init smem ----
    {
        uint32_t* hz = (uint32_t*)hbuf;
        for (int i = tid; i < 1920; i += 800) hz[i] = 0u;
        for (int i = tid; i < 9200; i += 800) {
            PtS[i] = __float2half(g_Pt[i]);
            PsS[i] = __float2half(g_Ps[i]);
        }
        for (int i = tid; i < 7 * 256; i += 800) {
            int r = i >> 8, tt = i & 255;
            int rr = min(row0 + r, BATCH - 1);
            int g = rr * 256 + tt;
            trajS[i] = (uint16_t)traj[g];
            idxP[i] = (uint32_t)tl[g] | ((uint32_t)tu[g] << 8) |
                      ((uint32_t)sl[g] << 16) | ((uint32_t)su[g] << 24);
            float utv = (float)tu_s[g], ltv = (float)tl_s[g];
            float usv = (float)su_s[g], lsv = (float)sl_s[g];
            float rdt = 1.f / fmaxf(utv + ltv, 1.f);
            float rds = 1.f / fmaxf(usv + lsv, 1.f);
            cT[i] = __floats2half2_rn(utv * rdt, ltv * rdt);
            cS[i] = __floats2half2_rn(usv * rds, lsv * rds);
        }
    }
    __syncthreads();

#define ISSUE(TT, B3)                                                           \
    {                                                                           \
        if (sact && (TT) < TSTEPS) {                                            \
            int gidx = (int)trajS[(r_s << 8) + (TT)];                           \
            const __half* srcp = g_Gloc + (size_t)gidx * 600 + c_s * 8;         \
            uint32_t dstp = stg_u32 + (uint32_t)(((B3) * 7 + r_s) * SRW + c_s * 8) * 2; \
            asm volatile("cp.async.cg.shared.global [%0], [%1], 16;"            \
                         :: "r"(dstp), "l"(srcp) : "memory");                   \
        }                                                                       \
        asm volatile("cp.async.commit_group;" ::: "memory");                    \
    }

    ISSUE(0, 0)
    ISSUE(1, 1)
    asm volatile("cp.async.wait_group 1;" ::: "memory");
    __syncthreads();

    float creg = 0.f;
    float* outp = out + (row0 + er7) * 100 + uj;
    const bool doout = evalid && (row0 + erow < BATCH);

#define STEPT(T, LAB, B3R, B3W, HNXT)                                           \
    {                                                                           \
        const __half* stgR = stg + (B3R) * (7 * SRW);                           \
        float c0[4] = {0.f, 0.f, 0.f, 0.f};                                     \
        float c1[4] = {0.f, 0.f, 0.f, 0.f};                                     \
        _Pragma("unroll")                                                       \
        for (int c = 0; c < 7; c++) {                                           \
            uint32_t a0, a1, a2, a3;                                            \
            asm volatile("ldmatrix.sync.aligned.m8n8.x4.shared.b16 "            \
                         "{%0,%1,%2,%3}, [%4];"                                 \
                         : "=r"(a0), "=r"(a1), "=r"(a2), "=r"(a3)               \
                         : "r"((LAB) + c * 32));                                \
            asm volatile("mma.sync.aligned.m16n8k16.row.col.f32.f16.f16.f32 "   \
                         "{%0,%1,%2,%3}, {%4,%5,%6,%7}, {%8,%9}, {%0,%1,%2,%3};"\
                         : "+f"(c0[0]), "+f"(c0[1]), "+f"(c0[2]), "+f"(c0[3])   \
                         : "r"(a0), "r"(a1), "r"(a2), "r"(a3),                  \
                           "r"(bf[c][0][0]), "r"(bf[c][0][1]));                 \
            asm volatile("mma.sync.aligned.m16n8k16.row.col.f32.f16.f16.f32 "   \
                         "{%0,%1,%2,%3}, {%4,%5,%6,%7}, {%8,%9}, {%0,%1,%2,%3};"\
                         : "+f"(c1[0]), "+f"(c1[1]), "+f"(c1[2]), "+f"(c1[3])   \
                         : "r"(a0), "r"(a1), "r"(a2), "r"(a3),                  \
                           "r"(bf[c][1][0]), "r"(bf[c][1][1]));                 \
        }                                                                       \
        float2 q0 = __half22float2(*(const __half2*)(stgR + pA0));              \
        float2 q1 = __half22float2(*(const __half2*)(stgR + pA0 + 8));          \
        float vA0 = c0[0] + q0.x, vB0 = c0[1] + q0.y;                           \
        float vA1 = c1[0] + q1.x, vB1 = c1[1] + q1.y;                           \
        float aA0 = fmaf(1.f / (1.f + __expf(-asl * vA0)), aal, abl);           \
        float aB0 = sigf(vB0);                                                  \
        float aA1 = fmaf(1.f / (1.f + __expf(-asl * vA1)), aal, abl);           \
        float aB1 = sigf(vB1);                                                  \
        float s0 = qodd ? aA0 : aA1;                                            \
        float s1 = qodd ? aB0 : aB1;                                            \
        float r0 = __shfl_xor_sync(0xffffffffu, s0, 1);                         \
        float r1 = __shfl_xor_sync(0xffffffffu, s1, 1);                         \
        float gi = qodd ? r0 : aA0;                                             \
        float gf = qodd ? r1 : aB0;                                             \
        float gg = qodd ? aA1 : r0;                                             \
        float go = qodd ? aB1 : r1;                                             \
        if (evalid) {                                                           \
            int ci = (er7 << 8) + (T);                                          \
            uint32_t ip = idxP[ci];                                             \
            int tli = ip & 255, tui = (ip >> 8) & 255;                          \
            int sli = (ip >> 16) & 255, sui = ip >> 24;                         \
            float2 ct = __half22float2(cT[ci]);                                 \
            float2 cs = __half22float2(cS[ci]);                                 \
            float tpre = __half2float(stgR[er7 * SRW + 400 + uj]);              \
            float spre = __half2float(stgR[er7 * SRW + 500 + uj]);              \
            float pt = tpre + ct.x * __half2float(PtS[tli * 100 + uj])          \
                            + ct.y * __half2float(PtS[tui * 100 + uj]);         \
            float ps = spre + cs.x * __half2float(PsS[sli * 100 + uj])          \
                            + cs.y * __half2float(PsS[sui * 100 + uj]);         \
            float tsg = sigf(pt) * sigf(ps);                                    \
            float cN = gf * creg + gi * tsg * gg;                               \
            creg = cN;                                                          \
            float h = go * tanh_fast(cN);                                       \
            (HNXT)[er7 * HS2 + uj] = __float2half(h);                           \
            if ((T) == TSTEPS - 1 && doout) *outp = h;                          \
        }                                                                       \
        ISSUE((T) + 2, B3W)                                                     \
        asm volatile("cp.async.wait_group 1;" ::: "memory");                    \
        __syncthreads();                                                        \
    }

    __half* hb0 = hbuf;
    __half* hb1 = hbuf + 16 * HS2;

    int b3a = 0;
#pragma unroll 1
    for (int s = 0; s < TSTEPS / 2; s++) {
        const int t0 = 2 * s;
        const int b3b  = (b3a == 2) ? 0 : b3a + 1;
        const int b3w0 = (b3b == 2) ? 0 : b3b + 1;
        const int b3w1 = b3a;
        STEPT(t0,     la0, b3a, b3w0, hb1)   // read h buf0, write h buf1
        STEPT(t0 + 1, la1, b3b, b3w1, hb0)   // read h buf1, write h buf0
        b3a = b3w0;
    }
#undef STEPT
#undef ISSUE
}

// =======================================================================
// launch
// =======================================================================
extern "C" void kernel_launch(void* const* d_in, const int* in_sizes, int n_in,
                              void* d_out, int out_size)
{
    (void)in_sizes; (void)n_in; (void)out_size;
    const int*   traj    = (const int*)d_in[0];
    const int*   tu      = (const int*)d_in[3];
    const int*   tl      = (const int*)d_in[4];
    const int*   tu_s    = (const int*)d_in[5];
    const int*   tl_s    = (const int*)d_in[6];
    const int*   su      = (const int*)d_in[7];
    const int*   sl      = (const int*)d_in[8];
    const int*   su_s    = (const int*)d_in[9];
    const int*   sl_s    = (const int*)d_in[10];
    const float* emb_loc = (const float*)d_in[11];
    const float* emb_t   = (const float*)d_in[12];
    const float* emb_s   = (const float*)d_in[13];
    const float* W_ih    = (const float*)d_in[14];
    const float* W_hh    = (const float*)d_in[15];
    const float* b       = (const float*)d_in[16];
    const float* W_xt    = (const float*)d_in[17];
    const float* W_tt    = (const float*)d_in[18];
    const float* b_t     = (const float*)d_in[19];
    const float* W_xs    = (const float*)d_in[20];
    const float* W_ss    = (const float*)d_in[21];
    const float* b_s     = (const float*)d_in[22];
    float* out = (float*)d_out;

    static bool attr_set = false;
    if (!attr_set) {
        cudaFuncSetAttribute(kernD, cudaFuncAttributeMaxDynamicSharedMemorySize,
                             DSM_TOTAL);
        attr_set = true;
    }

    const int NP = LOCN * 28 + 112 * 152;
    kernP<<<(NP + 255) / 256, 256>>>(emb_loc, W_ih, W_xt, W_xs);

    dim3 gA(5, (LOCN + 63) / 64);
    kernA<<<gA, 128>>>(b, b_t, b_s);

    kernB<<<(92 * 100 * 2 + 255) / 256, 256>>>(emb_t, W_tt, emb_s, W_ss);

    kernD<<<NCTA, 800, DSM_TOTAL>>>(W_hh, out, traj,
                                    tu, tl, tu_s, tl_s, su, sl, su_s, sl_s);
}

// round 15
// speedup vs baseline: 1.0886x; 1.0886x over previous
#include <cuda_runtime.h>
#include <cuda_fp16.h>
#include <cstdint>

#define LOCN   40001
#define BATCH  1024
#define TSTEPS 256

#define ROWS_PER_CTA 7
#define NCTA ((BATCH + ROWS_PER_CTA - 1) / ROWS_PER_CTA)   // 147
#define HS2 120                              // fp16 h row stride
#define SRW 608                              // staging row stride in halfs

// dynamic smem layout for kernD (bytes)
#define OFF_HBUF 0                            // 2*16*120*2 = 7680
#define OFF_ACTS 7680                         // 7*400*4    = 11200
#define OFF_STG  18880                        // 4*7*608*2  = 34048
#define OFF_TSG  52928                        // 2*704*2    = 2816
#define OFF_TRAJ 55744                        // 7*256*2    = 3584
#define OFF_IDXP 59328                        // 7*256*4    = 7168
#define OFF_CT   66496                        // 7*256*4    = 7168
#define OFF_CS   73664                        // 7*256*4    = 7168
#define OFF_PT   80832                        // 9200*2     = 18400
#define OFF_PS   99232                        // 9200*2     = 18400
#define DSM_TOTAL 117632

// ---------------- device scratch ----------------
__device__ __half g_Gloc[(size_t)LOCN * 600];                  // fp16: 48 MB (L2-resident)
__device__ float  g_Pt[92 * 100];
__device__ float  g_Ps[92 * 100];
__device__ __half g_emb16[(size_t)LOCN * 112];
__device__ __half g_W16[112 * 608];

// ---------------- helpers ----------------
__device__ __forceinline__ float sigf(float x) { return 1.f / (1.f + __expf(-x)); }
__device__ __forceinline__ float tanh_fast(float x) { return 1.f - 2.f / (1.f + __expf(2.f * x)); }

__device__ __forceinline__ uint32_t smem_u32(const void* p) {
    uint32_t a;
    asm("{ .reg .u64 t; cvta.to.shared.u64 t, %1; cvt.u32.u64 %0, t; }" : "=r"(a) : "l"(p));
    return a;
}

// =======================================================================
// Kernel P: one-time fp16 conversion (plain layout, as R13)
// =======================================================================
__global__ void kernP(const float* __restrict__ emb_loc,
                      const float* __restrict__ W_ih,
                      const float* __restrict__ W_xt,
                      const float* __restrict__ W_xs)
{
    const int NE = LOCN * 28;
    int i = blockIdx.x * blockDim.x + threadIdx.x;
    if (i < NE) {
        int row = i / 28, k4 = i % 28;
        int k = k4 * 4;
        float4 v = make_float4(0.f, 0.f, 0.f, 0.f);
        if (k < 100) v = *(const float4*)(emb_loc + (size_t)row * 100 + k);
        __half2 h0 = __floats2half2_rn(v.x, v.y);
        __half2 h1 = __floats2half2_rn(v.z, v.w);
        uint2 st;
        st.x = *reinterpret_cast<unsigned*>(&h0);
        st.y = *reinterpret_cast<unsigned*>(&h1);
        *(uint2*)(g_emb16 + (size_t)row * 112 + k) = st;
    } else {
        int j = i - NE;
        if (j < 112 * 152) {
            int k = j / 152, c4 = j % 152;
            int c = c4 * 4;
            float v[4] = {0.f, 0.f, 0.f, 0.f};
            if (k < 100) {
#pragma unroll
                for (int d = 0; d < 4; d++) {
                    int col = c + d;
                    if (col < 400)      v[d] = W_ih[k * 400 + col];
                    else if (col < 500) v[d] = W_xt[k * 100 + (col - 400)];
                    else if (col < 600) v[d] = W_xs[k * 100 + (col - 500)];
                }
            }
            __half2 h0 = __floats2half2_rn(v[0], v[1]);
            __half2 h1 = __floats2half2_rn(v[2], v[3]);
            uint2 st;
            st.x = *reinterpret_cast<unsigned*>(&h0);
            st.y = *reinterpret_cast<unsigned*>(&h1);
            *(uint2*)(g_W16 + k * 608 + c) = st;
        }
    }
}

// =======================================================================
// Kernel A (tensor-core, fp16 inputs) — as R13
// =======================================================================
#define KA_AS 120

__global__ void __launch_bounds__(128)
kernA(const float* __restrict__ b,
      const float* __restrict__ b_t,
      const float* __restrict__ b_s)
{
    __shared__ __align__(16) __half As[64 * KA_AS];
    __shared__ __align__(16) __half Bs[112 * KA_AS];

    const int tid = threadIdx.x;
    const int warp = tid >> 5, lane = tid & 31;
    const int n0 = blockIdx.x * 120;
    const int m0 = blockIdx.y * 64;

    for (int i = tid; i < 64 * 14; i += 128) {
        int r = i / 14, c = i % 14;
        int row = m0 + r; if (row >= LOCN) row = LOCN - 1;
        uint4 v = *(const uint4*)(g_emb16 + (size_t)row * 112 + c * 8);
        *(uint4*)(As + r * KA_AS + c * 8) = v;
    }
    for (int i = tid; i < 112 * 15; i += 128) {
        int k = i / 15, c = i % 15;
        uint4 v = *(const uint4*)(g_W16 + k * 608 + n0 + c * 8);
        *(uint4*)(Bs + k * KA_AS + c * 8) = v;
    }
    __syncthreads();

    const int g8 = lane >> 3, lr = lane & 7;

    float acc[15][4];
#pragma unroll
    for (int i = 0; i < 15; i++) { acc[i][0] = acc[i][1] = acc[i][2] = acc[i][3] = 0.f; }

    const int a_row = warp * 16 + (g8 & 1) * 8 + lr;
    const int a_kof = (g8 >> 1) * 8;
    const uint32_t a_base = smem_u32(&As[a_row * KA_AS + a_kof]);
    const int b_kof = (g8 & 1) * 8 + lr;
    const int b_nof = (g8 >> 1) * 8;
    const uint32_t b_base = smem_u32(&Bs[b_kof * KA_AS + b_nof]);
    const int b2_kof = ((lane >> 3) & 1) * 8 + lr;
    const uint32_t b2_base = smem_u32(&Bs[b2_kof * KA_AS + 112]);

#pragma unroll
    for (int kc = 0; kc < 7; kc++) {
        uint32_t a0, a1, a2, a3;
        asm volatile("ldmatrix.sync.aligned.m8n8.x4.shared.b16 {%0,%1,%2,%3}, [%4];"
                     : "=r"(a0), "=r"(a1), "=r"(a2), "=r"(a3)
                     : "r"(a_base + kc * 16 * 2));
#pragma unroll
        for (int pr = 0; pr < 7; pr++) {
            uint32_t b0, b1, b2, b3;
            asm volatile("ldmatrix.sync.aligned.m8n8.x4.trans.shared.b16 {%0,%1,%2,%3}, [%4];"
                         : "=r"(b0), "=r"(b1), "=r"(b2), "=r"(b3)
                         : "r"(b_base + (kc * 16 * KA_AS + pr * 16) * 2));
            asm volatile("mma.sync.aligned.m16n8k16.row.col.f32.f16.f16.f32 "
                         "{%0,%1,%2,%3}, {%4,%5,%6,%7}, {%8,%9}, {%0,%1,%2,%3};"
                         : "+f"(acc[2 * pr][0]), "+f"(acc[2 * pr][1]),
                           "+f"(acc[2 * pr][2]), "+f"(acc[2 * pr][3])
                         : "r"(a0), "r"(a1), "r"(a2), "r"(a3), "r"(b0), "r"(b1));
            asm volatile("mma.sync.aligned.m16n8k16.row.col.f32.f16.f16.f32 "
                         "{%0,%1,%2,%3}, {%4,%5,%6,%7}, {%8,%9}, {%0,%1,%2,%3};"
                         : "+f"(acc[2 * pr + 1][0]), "+f"(acc[2 * pr + 1][1]),
                           "+f"(acc[2 * pr + 1][2]), "+f"(acc[2 * pr + 1][3])
                         : "r"(a0), "r"(a1), "r"(a2), "r"(a3), "r"(b2), "r"(b3));
        }
        {
            uint32_t b0, b1;
            asm volatile("ldmatrix.sync.aligned.m8n8.x2.trans.shared.b16 {%0,%1}, [%2];"
                         : "=r"(b0), "=r"(b1)
                         : "r"(b2_base + kc * 16 * KA_AS * 2));
            asm volatile("mma.sync.aligned.m16n8k16.row.col.f32.f16.f16.f32 "
                         "{%0,%1,%2,%3}, {%4,%5,%6,%7}, {%8,%9}, {%0,%1,%2,%3};"
                         : "+f"(acc[14][0]), "+f"(acc[14][1]),
                           "+f"(acc[14][2]), "+f"(acc[14][3])
                         : "r"(a0), "r"(a1), "r"(a2), "r"(a3), "r"(b0), "r"(b1));
        }
    }

    const int row_lo = m0 + warp * 16 + (lane >> 2);
    const int row_hi = row_lo + 8;
#pragma unroll
    for (int nt = 0; nt < 15; nt++) {
        int col = n0 + nt * 8 + (lane & 3) * 2;
        float bias0, bias1;
        if (col < 400)      { bias0 = b[col];        bias1 = b[col + 1]; }
        else if (col < 500) { bias0 = b_t[col - 400]; bias1 = b_t[col - 399]; }
        else                { bias0 = b_s[col - 500]; bias1 = b_s[col - 499]; }
        __half2 lo = __floats2half2_rn(acc[nt][0] + bias0, acc[nt][1] + bias1);
        __half2 hi = __floats2half2_rn(acc[nt][2] + bias0, acc[nt][3] + bias1);
        if (row_lo < LOCN)
            *reinterpret_cast<unsigned*>(&g_Gloc[(size_t)row_lo * 600 + col]) =
                *reinterpret_cast<unsigned*>(&lo);
        if (row_hi < LOCN)
            *reinterpret_cast<unsigned*>(&g_Gloc[(size_t)row_hi * 600 + col]) =
                *reinterpret_cast<unsigned*>(&hi);
    }
}

// =======================================================================
// Kernel B (unchanged)
// =======================================================================
__global__ void kernB(const float* __restrict__ emb_t, const float* __restrict__ W_tt,
                      const float* __restrict__ emb_s, const float* __restrict__ W_ss)
{
    int i = blockIdx.x * blockDim.x + threadIdx.x;
    if (i >= 92 * 100 * 2) return;
    int which = i / 9200;
    int r = i % 9200;
    int s = r / 100, j = r % 100;
    const float* e = which ? emb_s : emb_t;
    const float* W = which ? W_ss : W_tt;
    float acc = 0.f;
#pragma unroll
    for (int d = 0; d < 12; d++) acc += e[s * 12 + d] * W[d * 100 + j];
    (which ? g_Ps : g_Pt)[s * 100 + j] = acc;
}

// =======================================================================
// Kernel D v13: R13 structure + quad-buffered staging (lead 2) + tsg
//  computed one step ahead into a smem ping-pong buffer (same thread
//  writes & reads -> no extra barrier; coalesced table access preserved).
// =======================================================================
__global__ void __launch_bounds__(800, 1)
kernD(const float* __restrict__ W_hh, float* __restrict__ out,
      const int* __restrict__ traj,
      const int* __restrict__ tu,   const int* __restrict__ tl,
      const int* __restrict__ tu_s, const int* __restrict__ tl_s,
      const int* __restrict__ su,   const int* __restrict__ sl,
      const int* __restrict__ su_s, const int* __restrict__ sl_s)
{
    extern __shared__ __align__(16) char dsm[];
    __half*   hbuf  = (__half*)(dsm + OFF_HBUF);   // [2][16][120]
    float*    acts  = (float*)(dsm + OFF_ACTS);    // [7][400]
    __half*   stg   = (__half*)(dsm + OFF_STG);    // [4][7][608]
    __half*   tsgS  = (__half*)(dsm + OFF_TSG);    // [2][704]
    uint16_t* trajS = (uint16_t*)(dsm + OFF_TRAJ); // [7][256]
    uint32_t* idxP  = (uint32_t*)(dsm + OFF_IDXP); // [7][256]
    __half2*  cTs   = (__half2*)(dsm + OFF_CT);    // [7][256]
    __half2*  cSs   = (__half2*)(dsm + OFF_CS);
    __half*   PtS   = (__half*)(dsm + OFF_PT);     // [92][100]
    __half*   PsS   = (__half*)(dsm + OFF_PS);

    const int tid = threadIdx.x;
    const int warp = tid >> 5, lane = tid & 31;
    const int row0 = blockIdx.x * ROWS_PER_CTA;

    // ---- B fragments: W_hh fp16, resident ----
    uint32_t bf[7][2][2];
    {
        const int bn = 16 * warp + (lane >> 2);
        const int bk = 2 * (lane & 3);
#pragma unroll
        for (int c = 0; c < 7; c++) {
#pragma unroll
            for (int t = 0; t < 2; t++) {
                int n = bn + 8 * t;
#pragma unroll
                for (int rr = 0; rr < 2; rr++) {
                    int k = 16 * c + bk + 8 * rr;
                    float lo = (k     < 100) ? W_hh[k * 400 + n]       : 0.f;
                    float hi = (k + 1 < 100) ? W_hh[(k + 1) * 400 + n] : 0.f;
                    __half2 hv = __floats2half2_rn(lo, hi);
                    bf[c][t][rr] = *reinterpret_cast<uint32_t*>(&hv);
                }
            }
        }
    }

    // ---- epilogue lane constants ----
    const int erow = lane >> 2;
    const bool evalid = (erow < ROWS_PER_CTA);
    const int ecol0 = 16 * warp + 2 * (lane & 3);
    const int g0 = ecol0 / 100, g1 = (ecol0 + 8) / 100;
    const float as0 = (g0 == 2) ? 2.f : 1.f, aA0 = as0, aB0 = (g0 == 2) ? -1.f : 0.f;
    const float as1 = (g1 == 2) ? 2.f : 1.f, aA1 = as1, aB1 = (g1 == 2) ? -1.f : 0.f;
    const int eoffA = (erow < 7 ? erow : 0) * SRW + ecol0;

    const uint32_t la0 = smem_u32(hbuf + (lane & 15) * HS2 + (lane >> 4) * 8);
    const uint32_t la1 = la0 + 16 * HS2 * 2;

    const int r_2 = tid / 100, j_2 = tid % 100;
    const bool p2act = (tid < 700);
    const bool p2out = (row0 + r_2 < BATCH);
    const int p2off = r_2 * SRW + 400 + j_2;

    const bool sact = (tid < 525);
    const int r_s = tid / 75, c_s = tid % 75;
    const uint32_t stg_u32 = smem_u32(stg);

    // ---- init smem ----
    {
        uint32_t* hz = (uint32_t*)hbuf;
        for (int i = tid; i < 1920; i += 800) hz[i] = 0u;
        for (int i = tid; i < 9200; i += 800) {
            PtS[i] = __float2half(g_Pt[i]);
            PsS[i] = __float2half(g_Ps[i]);
        }
        for (int i = tid; i < 7 * 256; i += 800) {
            int r = i >> 8, tt = i & 255;
            int rr = min(row0 + r, BATCH - 1);
            int g = rr * 256 + tt;
            trajS[i] = (uint16_t)traj[g];
            idxP[i] = (uint32_t)tl[g] | ((uint32_t)tu[g] << 8) |
                      ((uint32_t)sl[g] << 16) | ((uint32_t)su[g] << 24);
            float utv = (float)tu_s[g], ltv = (float)tl_s[g];
            float usv = (float)su_s[g], lsv = (float)sl_s[g];
            float rdt = 1.f / fmaxf(utv + ltv, 1.f);
            float rds = 1.f / fmaxf(usv + lsv, 1.f);
            cTs[i] = __floats2half2_rn(utv * rdt, ltv * rdt);
            cSs[i] = __floats2half2_rn(usv * rds, lsv * rds);
        }
    }
    __syncthreads();

#define ISSUE(TT)                                                               \
    {                                                                           \
        if (sact && (TT) < TSTEPS) {                                            \
            int gidx = (int)trajS[(r_s << 8) + (TT)];                           \
            const __half* srcp = g_Gloc + (size_t)gidx * 600 + c_s * 8;         \
            uint32_t dstp = stg_u32 +                                           \
                (uint32_t)((((TT) & 3) * 7 + r_s) * SRW + c_s * 8) * 2;         \
            asm volatile("cp.async.cg.shared.global [%0], [%1], 16;"            \
                         :: "r"(dstp), "l"(srcp) : "memory");                   \
        }                                                                       \
        asm volatile("cp.async.commit_group;" ::: "memory");                    \
    }

// tsg(T) -> tsgS[(T&1)*704 + tid]; reads stg[T&3] (guaranteed resident)
#define TSGCOMP(T)                                                              \
    if (p2act && (T) < TSTEPS) {                                                \
        int ci = (r_2 << 8) + (T);                                              \
        uint32_t ip = idxP[ci];                                                 \
        int tli = ip & 255, tui = (ip >> 8) & 255;                              \
        int sli = (ip >> 16) & 255, sui = ip >> 24;                             \
        float2 ct = __half22float2(cTs[ci]);                                    \
        float2 cs = __half22float2(cSs[ci]);                                    \
        const __half* sN = stg + ((T) & 3) * (7 * SRW);                         \
        float tpre = __half2float(sN[p2off]);                                   \
        float spre = __half2float(sN[p2off + 100]);                             \
        float pt = tpre + ct.x * __half2float(PtS[tli * 100 + j_2])             \
                        + ct.y * __half2float(PtS[tui * 100 + j_2]);            \
        float ps = spre + cs.x * __half2float(PsS[sli * 100 + j_2])             \
                        + cs.y * __half2float(PsS[sui * 100 + j_2]);            \
        tsgS[(((T) & 1) * 704) + tid] = __float2half(sigf(pt) * sigf(ps));      \
    }

    // prologue: stage t=0,1,2 ; all complete ; tsg(0)
    ISSUE(0)
    ISSUE(1)
    ISSUE(2)
    asm volatile("cp.async.wait_group 0;" ::: "memory");
    __syncthreads();
    TSGCOMP(0)

    float creg = 0.f;
    float* outp = out + (row0 + r_2) * 100 + j_2;
    float* aw0 = acts + (erow < 7 ? erow : 0) * 400 + ecol0;
    const float* ap2 = acts + r_2 * 400 + j_2;
    const int hslot_2 = j_2;
    __half* hn0 = hbuf + r_2 * HS2 + hslot_2;
    __half* hn1 = hn0 + 16 * HS2;

#define STEPT(T, LAB, HNP)                                                      \
    {                                                                           \
        const __half* stgR = stg + ((T) & 3) * (7 * SRW);                       \
        float c0[4] = {0.f, 0.f, 0.f, 0.f};                                     \
        float c1[4] = {0.f, 0.f, 0.f, 0.f};                                     \
        _Pragma("unroll")                                                       \
        for (int c = 0; c < 7; c++) {                                           \
            uint32_t a0, a1, a2, a3;                                            \
            asm volatile("ldmatrix.sync.aligned.m8n8.x4.shared.b16 "            \
                         "{%0,%1,%2,%3}, [%4];"                                 \
                         : "=r"(a0), "=r"(a1), "=r"(a2), "=r"(a3)               \
                         : "r"((LAB) + c * 32));                                \
            asm volatile("mma.sync.aligned.m16n8k16.row.col.f32.f16.f16.f32 "   \
                         "{%0,%1,%2,%3}, {%4,%5,%6,%7}, {%8,%9}, {%0,%1,%2,%3};"\
                         : "+f"(c0[0]), "+f"(c0[1]), "+f"(c0[2]), "+f"(c0[3])   \
                         : "r"(a0), "r"(a1), "r"(a2), "r"(a3),                  \
                           "r"(bf[c][0][0]), "r"(bf[c][0][1]));                 \
            asm volatile("mma.sync.aligned.m16n8k16.row.col.f32.f16.f16.f32 "   \
                         "{%0,%1,%2,%3}, {%4,%5,%6,%7}, {%8,%9}, {%0,%1,%2,%3};"\
                         : "+f"(c1[0]), "+f"(c1[1]), "+f"(c1[2]), "+f"(c1[3])   \
                         : "r"(a0), "r"(a1), "r"(a2), "r"(a3),                  \
                           "r"(bf[c][1][0]), "r"(bf[c][1][1]));                 \
        }                                                                       \
        if (evalid) {                                                           \
            float2 q0 = __half22float2(*(const __half2*)(stgR + eoffA));        \
            float2 q1 = __half22float2(*(const __half2*)(stgR + eoffA + 8));    \
            float vA = c0[0] + q0.x, vB = c0[1] + q0.y;                         \
            float vC = c1[0] + q1.x, vD = c1[1] + q1.y;                         \
            float sA = 1.f / (1.f + __expf(-as0 * vA));                         \
            float sB = 1.f / (1.f + __expf(-as0 * vB));                         \
            float sC = 1.f / (1.f + __expf(-as1 * vC));                         \
            float sD = 1.f / (1.f + __expf(-as1 * vD));                         \
            float2 e0 = make_float2(fmaf(sA, aA0, aB0), fmaf(sB, aA0, aB0));    \
            float2 e1 = make_float2(fmaf(sC, aA1, aB1), fmaf(sD, aA1, aB1));    \
            *(float2*)(aw0)     = e0;                                           \
            *(float2*)(aw0 + 8) = e1;                                           \
        }                                                                       \
        __syncthreads();                                                        \
        if (p2act) {                                                            \
            float gi = ap2[0], gf = ap2[100], gg = ap2[200], go = ap2[300];     \
            float tsg = __half2float(tsgS[(((T) & 1) * 704) + tid]);            \
            float cN = gf * creg + gi * tsg * gg;                               \
            creg = cN;                                                          \
            float h = go * tanh_fast(cN);                                       \
            *(HNP) = __float2half(h);                                           \
            if ((T) == TSTEPS - 1 && p2out) *outp = h;                          \
        }                                                                       \
        TSGCOMP((T) + 1)                                                        \
        ISSUE((T) + 3)                                                          \
        asm volatile("cp.async.wait_group 1;" ::: "memory");                    \
        __syncthreads();                                                        \
    }

#pragma unroll 1
    for (int s = 0; s < TSTEPS / 2; s++) {
        const int t0 = 2 * s;
        STEPT(t0,     la0, hn1)   // h in buf0, write h to buf1
        STEPT(t0 + 1, la1, hn0)   // h in buf1, write h to buf0
    }
#undef STEPT
#undef TSGCOMP
#undef ISSUE
}

// =======================================================================
// launch
// =======================================================================
extern "C" void kernel_launch(void* const* d_in, const int* in_sizes, int n_in,
                              void* d_out, int out_size)
{
    (void)in_sizes; (void)n_in; (void)out_size;
    const int*   traj    = (const int*)d_in[0];
    const int*   tu      = (const int*)d_in[3];
    const int*   tl      = (const int*)d_in[4];
    const int*   tu_s    = (const int*)d_in[5];
    const int*   tl_s    = (const int*)d_in[6];
    const int*   su      = (const int*)d_in[7];
    const int*   sl      = (const int*)d_in[8];
    const int*   su_s    = (const int*)d_in[9];
    const int*   sl_s    = (const int*)d_in[10];
    const float* emb_loc = (const float*)d_in[11];
    const float* emb_t   = (const float*)d_in[12];
    const float* emb_s   = (const float*)d_in[13];
    const float* W_ih    = (const float*)d_in[14];
    const float* W_hh    = (const float*)d_in[15];
    const float* b       = (const float*)d_in[16];
    const float* W_xt    = (const float*)d_in[17];
    const float* W_tt    = (const float*)d_in[18];
    const float* b_t     = (const float*)d_in[19];
    const float* W_xs    = (const float*)d_in[20];
    const float* W_ss    = (const float*)d_in[21];
    const float* b_s     = (const float*)d_in[22];
    float* out = (float*)d_out;

    static bool attr_set = false;
    if (!attr_set) {
        cudaFuncSetAttribute(kernD, cudaFuncAttributeMaxDynamicSharedMemorySize,
                             DSM_TOTAL);
        attr_set = true;
    }

    const int NP = LOCN * 28 + 112 * 152;
    kernP<<<(NP + 255) / 256, 256>>>(emb_loc, W_ih, W_xt, W_xs);

    dim3 gA(5, (LOCN + 63) / 64);
    kernA<<<gA, 128>>>(b, b_t, b_s);

    kernB<<<(92 * 100 * 2 + 255) / 256, 256>>>(emb_t, W_tt, emb_s, W_ss);

    kernD<<<NCTA, 800, DSM_TOTAL>>>(W_hh, out, traj,
                                    tu, tl, tu_s, tl_s, su, sl, su_s, sl_s);
}